// round 15
// baseline (speedup 1.0000x reference)
#include <cuda_runtime.h>
#include <cstdint>
#include <cstddef>

// Problem constants
#define TT   464
#define HH   256
#define BB   64
#define H4   1024
#define MROWS (BB*TT)          // 29696
#define KFLAT (TT*HH)          // 118784
#define NKC   116              // dense split-K chunks (1024 k each)

// ---------------- scratch (static device globals; no allocation) -------------
__device__ float g_Z[(size_t)MROWS * H4];        // x@W + b   (121.6 MB)
__device__ float g_seq[(size_t)BB * KFLAT];      // lstm outputs (30.4 MB)
__device__ float g_part[(size_t)NKC * BB * HH];  // dense partials (7.6 MB)
__device__ float g_dummy[2 * BB * HH];           // fallback for hT/cT

__device__ __forceinline__ float sigmoidf_(float x) {
    return 1.0f / (1.0f + expf(-x));
}

// ---------------- SMEM asm helpers -------------------------------------------
__device__ __forceinline__ float4 lds_v4f(unsigned addr) {
    float4 v;
    asm volatile("ld.shared.v4.f32 {%0,%1,%2,%3}, [%4];"
                 : "=f"(v.x), "=f"(v.y), "=f"(v.z), "=f"(v.w) : "r"(addr));
    return v;
}
__device__ __forceinline__ void sts_v4f(unsigned addr, float4 v) {
    asm volatile("st.shared.v4.f32 [%0], {%1,%2,%3,%4};"
                 :: "r"(addr), "f"(v.x), "f"(v.y), "f"(v.z), "f"(v.w));
}

// =============================================================================
// Kernel A: Z[m][n] = sum_k X[m][k]*W[k][n] + bias[n]
// M=29696, K=256, N=1024.  BM=128, BN=64, BK=16, 256 threads, 8x4 per thread,
// register double-buffered global loads.  (R13-proven.)
// =============================================================================
__global__ __launch_bounds__(256) void gemm_xw_kernel(
    const float* __restrict__ X, const float* __restrict__ W,
    const float* __restrict__ bias)
{
    __shared__ float As[16][128];
    __shared__ float Bs[16][64];

    const int tid = threadIdx.x;
    const int tx = tid & 15;          // 0..15  -> 4 cols
    const int ty = tid >> 4;          // 0..15  -> 8 rows
    const int mBase = blockIdx.y * 128;
    const int nBase = blockIdx.x * 64;

    const int lmA = tid >> 1;         // 0..127
    const int lkA = (tid & 1) * 8;    // 0 or 8
    const int lkB = tid >> 4;         // 0..15
    const int lnB = (tid & 15) * 4;

    float acc[8][4];
    #pragma unroll
    for (int i = 0; i < 8; i++)
        #pragma unroll
        for (int j = 0; j < 4; j++) acc[i][j] = 0.0f;

    const float* xRow = &X[(size_t)(mBase + lmA) * 256 + lkA];
    const float* wRow = &W[(size_t)lkB * H4 + nBase + lnB];

    float4 pv0 = *reinterpret_cast<const float4*>(xRow);
    float4 pv1 = *reinterpret_cast<const float4*>(xRow + 4);
    float4 pw  = *reinterpret_cast<const float4*>(wRow);

    #pragma unroll 1
    for (int t = 0; t < 16; t++) {
        As[lkA + 0][lmA] = pv0.x; As[lkA + 1][lmA] = pv0.y;
        As[lkA + 2][lmA] = pv0.z; As[lkA + 3][lmA] = pv0.w;
        As[lkA + 4][lmA] = pv1.x; As[lkA + 5][lmA] = pv1.y;
        As[lkA + 6][lmA] = pv1.z; As[lkA + 7][lmA] = pv1.w;
        *reinterpret_cast<float4*>(&Bs[lkB][lnB]) = pw;
        __syncthreads();

        if (t < 15) {
            const int k0 = (t + 1) * 16;
            pv0 = *reinterpret_cast<const float4*>(xRow + k0);
            pv1 = *reinterpret_cast<const float4*>(xRow + k0 + 4);
            pw  = *reinterpret_cast<const float4*>(wRow + (size_t)k0 * H4);
        }

        #pragma unroll
        for (int k = 0; k < 16; k++) {
            float4 a0 = *reinterpret_cast<const float4*>(&As[k][ty * 8]);
            float4 a1 = *reinterpret_cast<const float4*>(&As[k][ty * 8 + 4]);
            float4 b0 = *reinterpret_cast<const float4*>(&Bs[k][tx * 4]);
            float ar[8] = {a0.x, a0.y, a0.z, a0.w, a1.x, a1.y, a1.z, a1.w};
            float br[4] = {b0.x, b0.y, b0.z, b0.w};
            #pragma unroll
            for (int i = 0; i < 8; i++)
                #pragma unroll
                for (int j = 0; j < 4; j++)
                    acc[i][j] = fmaf(ar[i], br[j], acc[i][j]);
        }
        __syncthreads();
    }

    float4 bv = *reinterpret_cast<const float4*>(&bias[nBase + tx * 4]);
    #pragma unroll
    for (int i = 0; i < 8; i++) {
        float4 o;
        o.x = acc[i][0] + bv.x; o.y = acc[i][1] + bv.y;
        o.z = acc[i][2] + bv.z; o.w = acc[i][3] + bv.w;
        *reinterpret_cast<float4*>(&g_Z[(size_t)(mBase + ty * 8 + i) * H4 + nBase + tx * 4]) = o;
    }
}

// =============================================================================
// Kernel B: LSTM recurrence.  16 clusters x 8 CTAs, 256 threads each.
// CTA rank r holds 128 U columns (gate-interleaved) resident in SMEM, k-major
// Usk[k][128]: within a warp the 4 batch-lanes broadcast-share every u load
// (1 wavefront per LDS.128 for both u and h) -> ~1280 wf/step vs 2048-cyc
// FFMA floor, so the dot is FFMA-bound.  h in padded hbuf (stride 264).
// 256 threads = 2 kh-halves x 4 batches x 32 col-quads; kh partials merged via
// zbuf.  Fused cluster barrier per step (proven R5/R13); DSMEM h scatter as
// lane-paired u64 stores (proven R8).
// =============================================================================
#define CLSZ 8
#define GBAT 4
#define HSTR 264
#define USK_FLOATS (256 * 128)                 // 32768
#define HB_FLOATS  (2 * GBAT * HSTR)           // 2112
#define ZB_FLOATS  (2 * GBAT * 128)            // 1024
#define LSTM_SMEM_BYTES ((USK_FLOATS + HB_FLOATS + ZB_FLOATS) * 4)  // 143616

__global__ __cluster_dims__(CLSZ, 1, 1) __launch_bounds__(256, 1)
void lstm_kernel(const float* __restrict__ U,
                 const float* __restrict__ h0, const float* __restrict__ c0,
                 float* __restrict__ outHT, float* __restrict__ outCT)
{
    extern __shared__ float sm[];
    float* Usk  = sm;                       // [256][128]  k-major
    float* hbuf = sm + USK_FLOATS;          // [2][4][HSTR]
    float* zbuf = hbuf + HB_FLOATS;         // [2][4][128]  kh-partials

    const int tid = threadIdx.x;
    unsigned rank_u;
    asm("mov.u32 %0, %%cluster_ctarank;" : "=r"(rank_u));
    const int r   = (int)rank_u;
    const int gb0 = (blockIdx.x >> 3) * GBAT;

    // stage U slice, k-major: Usk[k][l] = U[k][(l>>5)*256 + r*32 + (l&31)]
    for (int idx = tid; idx < USK_FLOATS; idx += 256) {
        int k = idx >> 7, l = idx & 127;
        Usk[idx] = U[(size_t)k * H4 + (l >> 5) * 256 + r * 32 + (l & 31)];
    }
    // h0 into parity 0
    for (int idx = tid; idx < GBAT * HH; idx += 256) {
        int b = idx >> 8, k = idx & 255;
        hbuf[b * HSTR + k] = h0[(size_t)(gb0 + b) * HH + k];
    }

    // dot-phase roles
    const int w    = tid >> 5;
    const int lane = tid & 31;
    const int kh   = w >> 2;                   // k half (0/1)
    const int cg   = (w & 3) * 8 + (lane & 7); // col quad 0..31 (cols 4cg..4cg+3)
    const int bd_  = lane >> 3;                // batch 0..3

    const unsigned sm_b = (unsigned)__cvta_generic_to_shared(sm);
    const unsigned hb_b = sm_b + USK_FLOATS * 4;
    const unsigned zb_b = hb_b + HB_FLOATS * 4;
    const unsigned ua0  = sm_b + (unsigned)((kh * 128) * 128 + 4 * cg) * 4;
    const unsigned ha0  = hb_b + (unsigned)(bd_ * HSTR + kh * 128) * 4;
    const unsigned zst  = zb_b + (unsigned)((kh * 4 + bd_) * 128 + 4 * cg) * 4;

    // epilogue roles (tid < 128)
    const int bc = tid >> 5;
    const int dc = tid & 31;
    const int hdim = r * 32 + dc;
    float creg = 0.0f;
    const float* zp = g_Z + (size_t)(gb0 + bc) * TT * H4 + hdim;
    if (tid < 128) creg = c0[(size_t)(gb0 + bc) * HH + hdim];

    __syncthreads();
    asm volatile("barrier.cluster.arrive.aligned;" ::: "memory");
    asm volatile("barrier.cluster.wait.aligned;"  ::: "memory");

    for (int step = 0; step < TT; step++) {
        const int p = step & 1;

        // prefetch gate pre-activations (consumed after the ~2000-cyc dot)
        float z0 = 0.f, z1 = 0.f, z2 = 0.f, z3 = 0.f;
        if (tid < 128) {
            const float* zr = zp + (size_t)step * H4;
            z0 = __ldg(zr);       z1 = __ldg(zr + 256);
            z2 = __ldg(zr + 512); z3 = __ldg(zr + 768);
        }

        unsigned ua = ua0;
        unsigned ha = ha0 + (unsigned)(p * (GBAT * HSTR)) * 4;
        float4 acc = make_float4(0.f, 0.f, 0.f, 0.f);
        #pragma unroll 4
        for (int it = 0; it < 32; it++) {
            float4 h4 = lds_v4f(ha); ha += 16;
            float4 u;
            u = lds_v4f(ua);
            acc.x = fmaf(u.x, h4.x, acc.x); acc.y = fmaf(u.y, h4.x, acc.y);
            acc.z = fmaf(u.z, h4.x, acc.z); acc.w = fmaf(u.w, h4.x, acc.w);
            u = lds_v4f(ua + 512);
            acc.x = fmaf(u.x, h4.y, acc.x); acc.y = fmaf(u.y, h4.y, acc.y);
            acc.z = fmaf(u.z, h4.y, acc.z); acc.w = fmaf(u.w, h4.y, acc.w);
            u = lds_v4f(ua + 1024);
            acc.x = fmaf(u.x, h4.z, acc.x); acc.y = fmaf(u.y, h4.z, acc.y);
            acc.z = fmaf(u.z, h4.z, acc.z); acc.w = fmaf(u.w, h4.z, acc.w);
            u = lds_v4f(ua + 1536);
            acc.x = fmaf(u.x, h4.w, acc.x); acc.y = fmaf(u.y, h4.w, acc.y);
            acc.z = fmaf(u.z, h4.w, acc.z); acc.w = fmaf(u.w, h4.w, acc.w);
            ua += 2048;
        }
        sts_v4f(zst, acc);
        __syncthreads();

        if (tid < 128) {
            const float* zb = zbuf + bc * 128 + dc;
            float zi = zb[0]  + zb[512]      + z0;
            float zf = zb[32] + zb[512 + 32] + z1;
            float zg = zb[64] + zb[512 + 64] + z2;
            float zo = zb[96] + zb[512 + 96] + z3;
            float ig = sigmoidf_(zi);
            float fg = sigmoidf_(zf);
            creg = fg * creg + ig * fmaxf(zg, 0.0f);
            float hv = sigmoidf_(zo) * fmaxf(creg, 0.0f);

            g_seq[(size_t)(gb0 + bc) * KFLAT + step * HH + hdim] = hv;

            // pair lanes (dc even holds {h[dc], h[dc+1]}) -> u64 DSMEM stores
            float hpart = __shfl_xor_sync(0xffffffffu, hv, 1);
            if ((dc & 1) == 0) {
                unsigned long long pk;
                asm("mov.b64 %0, {%1,%2};" : "=l"(pk) : "f"(hv), "f"(hpart));
                unsigned la = hb_b +
                    (unsigned)(((p ^ 1) * GBAT + bc) * HSTR + hdim) * 4;
                #pragma unroll
                for (int rk = 0; rk < CLSZ; rk++) {
                    unsigned ra;
                    asm volatile("mapa.shared::cluster.u32 %0, %1, %2;"
                                 : "=r"(ra) : "r"(la), "r"(rk));
                    asm volatile("st.shared::cluster.u64 [%0], %1;"
                                 :: "r"(ra), "l"(pk) : "memory");
                }
            }
            if (step == TT - 1) {
                outHT[(size_t)(gb0 + bc) * HH + hdim] = hv;
                outCT[(size_t)(gb0 + bc) * HH + hdim] = creg;
            }
        }
        asm volatile("barrier.cluster.arrive.aligned;" ::: "memory");
        asm volatile("barrier.cluster.wait.aligned;"  ::: "memory");
    }
}

// =============================================================================
// Kernel C: dense split-K partials (R13-proven).
// M=64, N=256 (4 tiles of 64), K=118784 (116 chunks of 1024).
// =============================================================================
__global__ __launch_bounds__(256) void gemm_dense_kernel(const float* __restrict__ Wd)
{
    __shared__ float As[16][64];
    __shared__ float Bs[16][64];

    const int tid = threadIdx.x;
    const int tx = tid & 15;
    const int ty = tid >> 4;
    const int nBase = blockIdx.x * 64;
    const int kc = blockIdx.y;
    const int kBase = kc * 1024;

    const int lmA = tid >> 2;          // 0..63
    const int lkA = (tid & 3) * 4;     // 0,4,8,12
    const int lkB = tid >> 4;          // 0..15
    const int lnB = (tid & 15) * 4;

    float acc[4][4];
    #pragma unroll
    for (int i = 0; i < 4; i++)
        #pragma unroll
        for (int j = 0; j < 4; j++) acc[i][j] = 0.0f;

    const float* aRow = &g_seq[(size_t)lmA * KFLAT + kBase + lkA];
    const float* wRow = &Wd[(size_t)(kBase + lkB) * HH + nBase + lnB];

    float4 pa = *reinterpret_cast<const float4*>(aRow);
    float4 pw = *reinterpret_cast<const float4*>(wRow);

    #pragma unroll 1
    for (int it = 0; it < 64; it++) {
        As[lkA + 0][lmA] = pa.x; As[lkA + 1][lmA] = pa.y;
        As[lkA + 2][lmA] = pa.z; As[lkA + 3][lmA] = pa.w;
        *reinterpret_cast<float4*>(&Bs[lkB][lnB]) = pw;
        __syncthreads();

        if (it < 63) {
            const int k0 = (it + 1) * 16;
            pa = *reinterpret_cast<const float4*>(aRow + k0);
            pw = *reinterpret_cast<const float4*>(wRow + (size_t)k0 * HH);
        }

        #pragma unroll
        for (int k = 0; k < 16; k++) {
            float4 a = *reinterpret_cast<const float4*>(&As[k][ty * 4]);
            float4 b = *reinterpret_cast<const float4*>(&Bs[k][tx * 4]);
            float ar[4] = {a.x, a.y, a.z, a.w};
            float br[4] = {b.x, b.y, b.z, b.w};
            #pragma unroll
            for (int i = 0; i < 4; i++)
                #pragma unroll
                for (int j = 0; j < 4; j++)
                    acc[i][j] = fmaf(ar[i], br[j], acc[i][j]);
        }
        __syncthreads();
    }

    #pragma unroll
    for (int i = 0; i < 4; i++) {
        float4 o;
        o.x = acc[i][0]; o.y = acc[i][1]; o.z = acc[i][2]; o.w = acc[i][3];
        *reinterpret_cast<float4*>(
            &g_part[((size_t)kc * 64 + ty * 4 + i) * HH + nBase + tx * 4]) = o;
    }
}

// Final reduce + bias + relu -> core_output.  256 CTAs x 128 thr, k-split 2.
__global__ __launch_bounds__(128) void reduce_dense_kernel(
    const float* __restrict__ bd, float* __restrict__ outCore)
{
    __shared__ float s2[128];
    const int b  = blockIdx.x >> 2;
    const int nq = blockIdx.x & 3;
    const int n  = nq * 64 + (threadIdx.x & 63);
    const int kh = threadIdx.x >> 6;
    float s = 0.0f;
    #pragma unroll 8
    for (int kc = kh; kc < NKC; kc += 2)
        s += g_part[((size_t)kc * 64 + b) * HH + n];
    s2[threadIdx.x] = s;
    __syncthreads();
    if (kh == 0)
        outCore[(size_t)b * HH + n] = fmaxf(s + s2[threadIdx.x + 64] + bd[n], 0.0f);
}

// =============================================================================
extern "C" void kernel_launch(void* const* d_in, const int* in_sizes, int n_in,
                              void* d_out, int out_size)
{
    const float* X  = (const float*)d_in[0];  // [64,464,256]
    const float* h0 = (const float*)d_in[1];  // [64,256]
    const float* c0 = (const float*)d_in[2];  // [64,256]
    const float* W  = (const float*)d_in[3];  // [256,1024]
    const float* U  = (const float*)d_in[4];  // [256,1024]
    const float* bb = (const float*)d_in[5];  // [1024]
    const float* Wd = (const float*)d_in[6];  // [118784,256]
    const float* bd = (const float*)d_in[7];  // [256]
    float* out = (float*)d_out;

    float* outCore = out;
    float* outHT;
    float* outCT;
    if (out_size >= 3 * BB * HH) {
        outHT = out + BB * HH;
        outCT = out + 2 * BB * HH;
    } else {
        float* dummy = nullptr;
        cudaGetSymbolAddress((void**)&dummy, g_dummy);
        outHT = dummy;
        outCT = dummy + BB * HH;
    }

    cudaFuncSetAttribute(lstm_kernel,
                         cudaFuncAttributeMaxDynamicSharedMemorySize,
                         LSTM_SMEM_BYTES);

    // 1) Z = X@W + b
    gemm_xw_kernel<<<dim3(H4 / 64, MROWS / 128), 256>>>(X, W, bb);

    // 2) recurrence (16 clusters x 8 CTAs)
    lstm_kernel<<<128, 256, LSTM_SMEM_BYTES>>>(U, h0, c0, outHT, outCT);

    // 3) dense split-K + reduce
    gemm_dense_kernel<<<dim3(HH / 64, NKC), 256>>>(Wd);
    reduce_dense_kernel<<<256, 128>>>(bd, outCore);
}

// round 17
// speedup vs baseline: 1.0096x; 1.0096x over previous
#include <cuda_runtime.h>
#include <cstdint>
#include <cstddef>

// Problem constants
#define TT   464
#define HH   256
#define BB   64
#define H4   1024
#define MROWS (BB*TT)          // 29696
#define KFLAT (TT*HH)          // 118784
#define NKC   116              // dense split-K chunks (1024 k each)

// ---------------- scratch (static device globals; no allocation) -------------
__device__ float g_Z[(size_t)MROWS * H4];        // x@W + b   (121.6 MB)
__device__ float g_seq[(size_t)BB * KFLAT];      // lstm outputs (30.4 MB)
__device__ float g_part[(size_t)NKC * BB * HH];  // dense partials (7.6 MB)
__device__ float g_dummy[2 * BB * HH];           // fallback for hT/cT

__device__ __forceinline__ float sigmoidf_(float x) {
    return 1.0f / (1.0f + expf(-x));
}

// ---------------- SMEM asm helpers -------------------------------------------
__device__ __forceinline__ float4 lds_v4f(unsigned addr) {
    float4 v;
    asm volatile("ld.shared.v4.f32 {%0,%1,%2,%3}, [%4];"
                 : "=f"(v.x), "=f"(v.y), "=f"(v.z), "=f"(v.w) : "r"(addr));
    return v;
}
__device__ __forceinline__ void sts_v4f(unsigned addr, float4 v) {
    asm volatile("st.shared.v4.f32 [%0], {%1,%2,%3,%4};"
                 :: "r"(addr), "f"(v.x), "f"(v.y), "f"(v.z), "f"(v.w));
}

// =============================================================================
// Kernel A: Z[m][n] = sum_k X[m][k]*W[k][n] + bias[n]
// M=29696, K=256, N=1024.  BM=128, BN=64, BK=16, 256 threads, 8x4 per thread,
// register double-buffered global loads.  (R13-proven.)
// =============================================================================
__global__ __launch_bounds__(256) void gemm_xw_kernel(
    const float* __restrict__ X, const float* __restrict__ W,
    const float* __restrict__ bias)
{
    __shared__ float As[16][128];
    __shared__ float Bs[16][64];

    const int tid = threadIdx.x;
    const int tx = tid & 15;          // 0..15  -> 4 cols
    const int ty = tid >> 4;          // 0..15  -> 8 rows
    const int mBase = blockIdx.y * 128;
    const int nBase = blockIdx.x * 64;

    const int lmA = tid >> 1;         // 0..127
    const int lkA = (tid & 1) * 8;    // 0 or 8
    const int lkB = tid >> 4;         // 0..15
    const int lnB = (tid & 15) * 4;

    float acc[8][4];
    #pragma unroll
    for (int i = 0; i < 8; i++)
        #pragma unroll
        for (int j = 0; j < 4; j++) acc[i][j] = 0.0f;

    const float* xRow = &X[(size_t)(mBase + lmA) * 256 + lkA];
    const float* wRow = &W[(size_t)lkB * H4 + nBase + lnB];

    float4 pv0 = *reinterpret_cast<const float4*>(xRow);
    float4 pv1 = *reinterpret_cast<const float4*>(xRow + 4);
    float4 pw  = *reinterpret_cast<const float4*>(wRow);

    #pragma unroll 1
    for (int t = 0; t < 16; t++) {
        As[lkA + 0][lmA] = pv0.x; As[lkA + 1][lmA] = pv0.y;
        As[lkA + 2][lmA] = pv0.z; As[lkA + 3][lmA] = pv0.w;
        As[lkA + 4][lmA] = pv1.x; As[lkA + 5][lmA] = pv1.y;
        As[lkA + 6][lmA] = pv1.z; As[lkA + 7][lmA] = pv1.w;
        *reinterpret_cast<float4*>(&Bs[lkB][lnB]) = pw;
        __syncthreads();

        if (t < 15) {
            const int k0 = (t + 1) * 16;
            pv0 = *reinterpret_cast<const float4*>(xRow + k0);
            pv1 = *reinterpret_cast<const float4*>(xRow + k0 + 4);
            pw  = *reinterpret_cast<const float4*>(wRow + (size_t)k0 * H4);
        }

        #pragma unroll
        for (int k = 0; k < 16; k++) {
            float4 a0 = *reinterpret_cast<const float4*>(&As[k][ty * 8]);
            float4 a1 = *reinterpret_cast<const float4*>(&As[k][ty * 8 + 4]);
            float4 b0 = *reinterpret_cast<const float4*>(&Bs[k][tx * 4]);
            float ar[8] = {a0.x, a0.y, a0.z, a0.w, a1.x, a1.y, a1.z, a1.w};
            float br[4] = {b0.x, b0.y, b0.z, b0.w};
            #pragma unroll
            for (int i = 0; i < 8; i++)
                #pragma unroll
                for (int j = 0; j < 4; j++)
                    acc[i][j] = fmaf(ar[i], br[j], acc[i][j]);
        }
        __syncthreads();
    }

    float4 bv = *reinterpret_cast<const float4*>(&bias[nBase + tx * 4]);
    #pragma unroll
    for (int i = 0; i < 8; i++) {
        float4 o;
        o.x = acc[i][0] + bv.x; o.y = acc[i][1] + bv.y;
        o.z = acc[i][2] + bv.z; o.w = acc[i][3] + bv.w;
        *reinterpret_cast<float4*>(&g_Z[(size_t)(mBase + ty * 8 + i) * H4 + nBase + tx * 4]) = o;
    }
}

// =============================================================================
// Kernel B: LSTM recurrence.  16 clusters x 8 CTAs, 256 threads each.
// CTA rank r holds 128 U columns (gate-interleaved, l = gate*32+d) resident in
// SMEM, k-major Usk[k][128].  Register-blocked dot: each thread computes
// 8 cols x 2 batches over a 32-k slice (warp w = k-slice w).  Per thread per
// step: 80 LDS.128 / 512 FFMA (ratio 6.4 vs 2.7 in R13) -> dot becomes
// FFMA-issue-bound (~2048 cyc) instead of LDS-bound (~3100).
// kh partials merged via zbuf (8-way, conflict-free scalar loads).
// Fused cluster barrier per step + scalar f32 DSMEM scatter (R13-proven).
// =============================================================================
#define CLSZ 8
#define GBAT 4
#define HSTR 264
#define USK_FLOATS (256 * 128)                 // 32768
#define HB_FLOATS  (2 * GBAT * HSTR)           // 2112
#define ZB_FLOATS  (8 * GBAT * 128)            // 4096
#define LSTM_SMEM_BYTES ((USK_FLOATS + HB_FLOATS + ZB_FLOATS) * 4)  // 155904

__global__ __cluster_dims__(CLSZ, 1, 1) __launch_bounds__(256, 1)
void lstm_kernel(const float* __restrict__ U,
                 const float* __restrict__ h0, const float* __restrict__ c0,
                 float* __restrict__ outHT, float* __restrict__ outCT)
{
    extern __shared__ float sm[];
    float* Usk  = sm;                       // [256][128]  k-major
    float* hbuf = sm + USK_FLOATS;          // [2][4][HSTR]
    float* zbuf = hbuf + HB_FLOATS;         // [8][4][128]  kh-partials

    const int tid = threadIdx.x;
    unsigned rank_u;
    asm("mov.u32 %0, %%cluster_ctarank;" : "=r"(rank_u));
    const int r   = (int)rank_u;
    const int gb0 = (blockIdx.x >> 3) * GBAT;

    // stage U slice, k-major: Usk[k][l] = U[k][(l>>5)*256 + r*32 + (l&31)]
    for (int idx = tid; idx < USK_FLOATS; idx += 256) {
        int k = idx >> 7, l = idx & 127;
        Usk[idx] = U[(size_t)k * H4 + (l >> 5) * 256 + r * 32 + (l & 31)];
    }
    // h0 into parity 0
    for (int idx = tid; idx < GBAT * HH; idx += 256) {
        int b = idx >> 8, k = idx & 255;
        hbuf[b * HSTR + k] = h0[(size_t)(gb0 + b) * HH + k];
    }

    // dot-phase roles: warp w = k-slice [32w, 32w+32); lane: bp = lane>>4,
    // cg = lane&15 -> cols 8cg..8cg+7 (of the 128 gate-interleaved cols);
    // batches b0 = 2bp, b1 = 2bp+1.
    const int w    = tid >> 5;
    const int lane = tid & 31;
    const int bp   = lane >> 4;
    const int cg   = lane & 15;
    const int k0s  = 32 * w;
    const int b0   = 2 * bp;
    const int b1   = 2 * bp + 1;

    const unsigned sm_b = (unsigned)__cvta_generic_to_shared(sm);
    const unsigned hb_b = sm_b + USK_FLOATS * 4;
    const unsigned zb_b = hb_b + HB_FLOATS * 4;
    const unsigned ua0  = sm_b + (unsigned)(k0s * 128 + 8 * cg) * 4;
    const unsigned hA0  = hb_b + (unsigned)(b0 * HSTR + k0s) * 4;
    const unsigned hB0  = hb_b + (unsigned)(b1 * HSTR + k0s) * 4;
    const unsigned zstA = zb_b + (unsigned)((w * 4 + b0) * 128 + 8 * cg) * 4;
    const unsigned zstB = zb_b + (unsigned)((w * 4 + b1) * 128 + 8 * cg) * 4;

    // epilogue roles (tid < 128)
    const int bc = tid >> 5;
    const int dc = tid & 31;
    const int hdim = r * 32 + dc;
    float creg = 0.0f;
    const float* zp = g_Z + (size_t)(gb0 + bc) * TT * H4 + hdim;
    if (tid < 128) creg = c0[(size_t)(gb0 + bc) * HH + hdim];

    __syncthreads();
    asm volatile("barrier.cluster.arrive.aligned;" ::: "memory");
    asm volatile("barrier.cluster.wait.aligned;"  ::: "memory");

    for (int step = 0; step < TT; step++) {
        const int p = step & 1;

        // prefetch gate pre-activations (consumed after the ~2000-cyc dot)
        float z0 = 0.f, z1 = 0.f, z2 = 0.f, z3 = 0.f;
        if (tid < 128) {
            const float* zr = zp + (size_t)step * H4;
            z0 = __ldg(zr);       z1 = __ldg(zr + 256);
            z2 = __ldg(zr + 512); z3 = __ldg(zr + 768);
        }

        float accA[8], accB[8];
        #pragma unroll
        for (int i = 0; i < 8; i++) { accA[i] = 0.f; accB[i] = 0.f; }

        unsigned ua = ua0;
        unsigned hA = hA0 + (unsigned)(p * (GBAT * HSTR)) * 4;
        unsigned hB = hB0 + (unsigned)(p * (GBAT * HSTR)) * 4;

        #pragma unroll
        for (int kq = 0; kq < 8; kq++) {
            float4 ha = lds_v4f(hA); hA += 16;
            float4 hb = lds_v4f(hB); hB += 16;

            float4 u0, u1;
            // k + 0
            u0 = lds_v4f(ua); u1 = lds_v4f(ua + 16); ua += 512;
            accA[0] = fmaf(u0.x, ha.x, accA[0]); accA[1] = fmaf(u0.y, ha.x, accA[1]);
            accA[2] = fmaf(u0.z, ha.x, accA[2]); accA[3] = fmaf(u0.w, ha.x, accA[3]);
            accA[4] = fmaf(u1.x, ha.x, accA[4]); accA[5] = fmaf(u1.y, ha.x, accA[5]);
            accA[6] = fmaf(u1.z, ha.x, accA[6]); accA[7] = fmaf(u1.w, ha.x, accA[7]);
            accB[0] = fmaf(u0.x, hb.x, accB[0]); accB[1] = fmaf(u0.y, hb.x, accB[1]);
            accB[2] = fmaf(u0.z, hb.x, accB[2]); accB[3] = fmaf(u0.w, hb.x, accB[3]);
            accB[4] = fmaf(u1.x, hb.x, accB[4]); accB[5] = fmaf(u1.y, hb.x, accB[5]);
            accB[6] = fmaf(u1.z, hb.x, accB[6]); accB[7] = fmaf(u1.w, hb.x, accB[7]);
            // k + 1
            u0 = lds_v4f(ua); u1 = lds_v4f(ua + 16); ua += 512;
            accA[0] = fmaf(u0.x, ha.y, accA[0]); accA[1] = fmaf(u0.y, ha.y, accA[1]);
            accA[2] = fmaf(u0.z, ha.y, accA[2]); accA[3] = fmaf(u0.w, ha.y, accA[3]);
            accA[4] = fmaf(u1.x, ha.y, accA[4]); accA[5] = fmaf(u1.y, ha.y, accA[5]);
            accA[6] = fmaf(u1.z, ha.y, accA[6]); accA[7] = fmaf(u1.w, ha.y, accA[7]);
            accB[0] = fmaf(u0.x, hb.y, accB[0]); accB[1] = fmaf(u0.y, hb.y, accB[1]);
            accB[2] = fmaf(u0.z, hb.y, accB[2]); accB[3] = fmaf(u0.w, hb.y, accB[3]);
            accB[4] = fmaf(u1.x, hb.y, accB[4]); accB[5] = fmaf(u1.y, hb.y, accB[5]);
            accB[6] = fmaf(u1.z, hb.y, accB[6]); accB[7] = fmaf(u1.w, hb.y, accB[7]);
            // k + 2
            u0 = lds_v4f(ua); u1 = lds_v4f(ua + 16); ua += 512;
            accA[0] = fmaf(u0.x, ha.z, accA[0]); accA[1] = fmaf(u0.y, ha.z, accA[1]);
            accA[2] = fmaf(u0.z, ha.z, accA[2]); accA[3] = fmaf(u0.w, ha.z, accA[3]);
            accA[4] = fmaf(u1.x, ha.z, accA[4]); accA[5] = fmaf(u1.y, ha.z, accA[5]);
            accA[6] = fmaf(u1.z, ha.z, accA[6]); accA[7] = fmaf(u1.w, ha.z, accA[7]);
            accB[0] = fmaf(u0.x, hb.z, accB[0]); accB[1] = fmaf(u0.y, hb.z, accB[1]);
            accB[2] = fmaf(u0.z, hb.z, accB[2]); accB[3] = fmaf(u0.w, hb.z, accB[3]);
            accB[4] = fmaf(u1.x, hb.z, accB[4]); accB[5] = fmaf(u1.y, hb.z, accB[5]);
            accB[6] = fmaf(u1.z, hb.z, accB[6]); accB[7] = fmaf(u1.w, hb.z, accB[7]);
            // k + 3
            u0 = lds_v4f(ua); u1 = lds_v4f(ua + 16); ua += 512;
            accA[0] = fmaf(u0.x, ha.w, accA[0]); accA[1] = fmaf(u0.y, ha.w, accA[1]);
            accA[2] = fmaf(u0.z, ha.w, accA[2]); accA[3] = fmaf(u0.w, ha.w, accA[3]);
            accA[4] = fmaf(u1.x, ha.w, accA[4]); accA[5] = fmaf(u1.y, ha.w, accA[5]);
            accA[6] = fmaf(u1.z, ha.w, accA[6]); accA[7] = fmaf(u1.w, ha.w, accA[7]);
            accB[0] = fmaf(u0.x, hb.w, accB[0]); accB[1] = fmaf(u0.y, hb.w, accB[1]);
            accB[2] = fmaf(u0.z, hb.w, accB[2]); accB[3] = fmaf(u0.w, hb.w, accB[3]);
            accB[4] = fmaf(u1.x, hb.w, accB[4]); accB[5] = fmaf(u1.y, hb.w, accB[5]);
            accB[6] = fmaf(u1.z, hb.w, accB[6]); accB[7] = fmaf(u1.w, hb.w, accB[7]);
        }

        sts_v4f(zstA,      make_float4(accA[0], accA[1], accA[2], accA[3]));
        sts_v4f(zstA + 16, make_float4(accA[4], accA[5], accA[6], accA[7]));
        sts_v4f(zstB,      make_float4(accB[0], accB[1], accB[2], accB[3]));
        sts_v4f(zstB + 16, make_float4(accB[4], accB[5], accB[6], accB[7]));
        __syncthreads();

        if (tid < 128) {
            const float* zb = zbuf + bc * 128 + dc;
            float zi = z0, zf = z1, zg = z2, zo = z3;
            #pragma unroll
            for (int khi = 0; khi < 8; khi++) {
                const float* q = zb + khi * 512;
                zi += q[0]; zf += q[32]; zg += q[64]; zo += q[96];
            }
            float ig = sigmoidf_(zi);
            float fg = sigmoidf_(zf);
            creg = fg * creg + ig * fmaxf(zg, 0.0f);
            float hv = sigmoidf_(zo) * fmaxf(creg, 0.0f);

            g_seq[(size_t)(gb0 + bc) * KFLAT + step * HH + hdim] = hv;

            unsigned la = hb_b +
                (unsigned)(((p ^ 1) * GBAT + bc) * HSTR + hdim) * 4;
            #pragma unroll
            for (int rk = 0; rk < CLSZ; rk++) {
                unsigned ra;
                asm volatile("mapa.shared::cluster.u32 %0, %1, %2;"
                             : "=r"(ra) : "r"(la), "r"(rk));
                asm volatile("st.shared::cluster.f32 [%0], %1;"
                             :: "r"(ra), "f"(hv) : "memory");
            }
            if (step == TT - 1) {
                outHT[(size_t)(gb0 + bc) * HH + hdim] = hv;
                outCT[(size_t)(gb0 + bc) * HH + hdim] = creg;
            }
        }
        asm volatile("barrier.cluster.arrive.aligned;" ::: "memory");
        asm volatile("barrier.cluster.wait.aligned;"  ::: "memory");
    }
}

// =============================================================================
// Kernel C: dense split-K partials (R13-proven).
// M=64, N=256 (4 tiles of 64), K=118784 (116 chunks of 1024).
// =============================================================================
__global__ __launch_bounds__(256) void gemm_dense_kernel(const float* __restrict__ Wd)
{
    __shared__ float As[16][64];
    __shared__ float Bs[16][64];

    const int tid = threadIdx.x;
    const int tx = tid & 15;
    const int ty = tid >> 4;
    const int nBase = blockIdx.x * 64;
    const int kc = blockIdx.y;
    const int kBase = kc * 1024;

    const int lmA = tid >> 2;          // 0..63
    const int lkA = (tid & 3) * 4;     // 0,4,8,12
    const int lkB = tid >> 4;          // 0..15
    const int lnB = (tid & 15) * 4;

    float acc[4][4];
    #pragma unroll
    for (int i = 0; i < 4; i++)
        #pragma unroll
        for (int j = 0; j < 4; j++) acc[i][j] = 0.0f;

    const float* aRow = &g_seq[(size_t)lmA * KFLAT + kBase + lkA];
    const float* wRow = &Wd[(size_t)(kBase + lkB) * HH + nBase + lnB];

    float4 pa = *reinterpret_cast<const float4*>(aRow);
    float4 pw = *reinterpret_cast<const float4*>(wRow);

    #pragma unroll 1
    for (int it = 0; it < 64; it++) {
        As[lkA + 0][lmA] = pa.x; As[lkA + 1][lmA] = pa.y;
        As[lkA + 2][lmA] = pa.z; As[lkA + 3][lmA] = pa.w;
        *reinterpret_cast<float4*>(&Bs[lkB][lnB]) = pw;
        __syncthreads();

        if (it < 63) {
            const int k0 = (it + 1) * 16;
            pa = *reinterpret_cast<const float4*>(aRow + k0);
            pw = *reinterpret_cast<const float4*>(wRow + (size_t)k0 * HH);
        }

        #pragma unroll
        for (int k = 0; k < 16; k++) {
            float4 a = *reinterpret_cast<const float4*>(&As[k][ty * 4]);
            float4 b = *reinterpret_cast<const float4*>(&Bs[k][tx * 4]);
            float ar[4] = {a.x, a.y, a.z, a.w};
            float br[4] = {b.x, b.y, b.z, b.w};
            #pragma unroll
            for (int i = 0; i < 4; i++)
                #pragma unroll
                for (int j = 0; j < 4; j++)
                    acc[i][j] = fmaf(ar[i], br[j], acc[i][j]);
        }
        __syncthreads();
    }

    #pragma unroll
    for (int i = 0; i < 4; i++) {
        float4 o;
        o.x = acc[i][0]; o.y = acc[i][1]; o.z = acc[i][2]; o.w = acc[i][3];
        *reinterpret_cast<float4*>(
            &g_part[((size_t)kc * 64 + ty * 4 + i) * HH + nBase + tx * 4]) = o;
    }
}

// Final reduce + bias + relu -> core_output.  256 CTAs x 128 thr, k-split 2.
__global__ __launch_bounds__(128) void reduce_dense_kernel(
    const float* __restrict__ bd, float* __restrict__ outCore)
{
    __shared__ float s2[128];
    const int b  = blockIdx.x >> 2;
    const int nq = blockIdx.x & 3;
    const int n  = nq * 64 + (threadIdx.x & 63);
    const int kh = threadIdx.x >> 6;
    float s = 0.0f;
    #pragma unroll 8
    for (int kc = kh; kc < NKC; kc += 2)
        s += g_part[((size_t)kc * 64 + b) * HH + n];
    s2[threadIdx.x] = s;
    __syncthreads();
    if (kh == 0)
        outCore[(size_t)b * HH + n] = fmaxf(s + s2[threadIdx.x + 64] + bd[n], 0.0f);
}

// =============================================================================
extern "C" void kernel_launch(void* const* d_in, const int* in_sizes, int n_in,
                              void* d_out, int out_size)
{
    const float* X  = (const float*)d_in[0];  // [64,464,256]
    const float* h0 = (const float*)d_in[1];  // [64,256]
    const float* c0 = (const float*)d_in[2];  // [64,256]
    const float* W  = (const float*)d_in[3];  // [256,1024]
    const float* U  = (const float*)d_in[4];  // [256,1024]
    const float* bb = (const float*)d_in[5];  // [1024]
    const float* Wd = (const float*)d_in[6];  // [118784,256]
    const float* bd = (const float*)d_in[7];  // [256]
    float* out = (float*)d_out;

    float* outCore = out;
    float* outHT;
    float* outCT;
    if (out_size >= 3 * BB * HH) {
        outHT = out + BB * HH;
        outCT = out + 2 * BB * HH;
    } else {
        float* dummy = nullptr;
        cudaGetSymbolAddress((void**)&dummy, g_dummy);
        outHT = dummy;
        outCT = dummy + BB * HH;
    }

    cudaFuncSetAttribute(lstm_kernel,
                         cudaFuncAttributeMaxDynamicSharedMemorySize,
                         LSTM_SMEM_BYTES);

    // 1) Z = X@W + b
    gemm_xw_kernel<<<dim3(H4 / 64, MROWS / 128), 256>>>(X, W, bb);

    // 2) recurrence (16 clusters x 8 CTAs)
    lstm_kernel<<<128, 256, LSTM_SMEM_BYTES>>>(U, h0, c0, outHT, outCT);

    // 3) dense split-K + reduce
    gemm_dense_kernel<<<dim3(HH / 64, NKC), 256>>>(Wd);
    reduce_dense_kernel<<<256, 128>>>(bd, outCore);
}